// round 13
// baseline (speedup 1.0000x reference)
#include <cuda_runtime.h>
#include <math.h>
#include <stdint.h>

// Problem constants
#define HD   4096
#define IS   2048
#define NE   16
#define NK   4
#define SIW  2048
#define TMAX 4096

// GEMM tile: CTA 128x128, 8 warps (2M x 4N), warp tile 64x32, K-chunk 32
#define BM   128
#define BN   128
#define BKT  32
#define LSTR 36                              // padded row stride (floats)
#define SM_A_FLOATS (BM * LSTR)              // 4608
#define SM_STAGE    (2 * SM_A_FLOATS)        // A + B per stage = 9216 floats
#define STAGE_BYTES (SM_STAGE * 4)           // 36864
#define DSMEM_BYTES (2 * STAGE_BYTES)        // 73728

// ---------------- static device scratch ----------------
__device__ int   d_cnt[NE];
__device__ int   d_tok[NE * TMAX];
__device__ float d_wgt[NE * TMAX];
__device__ float d_bufG[(size_t)NE * TMAX * IS];   // routed gate proj -> z (rounded)
__device__ float d_bufU[(size_t)NE * TMAX * IS];   // routed up proj
__device__ float d_sG[(size_t)TMAX * SIW];         // shared gate -> z (rounded)
__device__ float d_sU[(size_t)TMAX * SIW];         // shared up

// ---------------- helpers ----------------
__device__ __forceinline__ uint32_t smem_u32(const void* p) {
    uint32_t a;
    asm("{ .reg .u64 t; cvta.to.shared.u64 t, %1; cvt.u32.u64 %0, t; }" : "=r"(a) : "l"(p));
    return a;
}
__device__ __forceinline__ unsigned f2tf32(float f) {
    unsigned r;
    asm("cvt.rna.tf32.f32 %0, %1;" : "=r"(r) : "f"(f));
    return r;
}
__device__ __forceinline__ float rndf(float v) {
    return __uint_as_float(f2tf32(v));
}
__device__ __forceinline__ unsigned cvt_bits(unsigned raw) {
    return f2tf32(__uint_as_float(raw));
}
#define CPA16(dst, src) \
    asm volatile("cp.async.cg.shared.global [%0], [%1], 16;" :: "r"(dst), "l"(src))
#define CPA_COMMIT() asm volatile("cp.async.commit_group;")
#define CPA_WAIT(n)  asm volatile("cp.async.wait_group %0;" :: "n"(n))

#define LDSM4(r0, r1, r2, r3, addr) \
    asm volatile("ldmatrix.sync.aligned.m8n8.x4.shared.b16 {%0,%1,%2,%3}, [%4];" \
                 : "=r"(r0), "=r"(r1), "=r"(r2), "=r"(r3) : "r"(addr))

__device__ __forceinline__ void mma_tf32(float* d, const unsigned* a, unsigned b0, unsigned b1) {
    asm volatile(
        "mma.sync.aligned.m16n8k8.row.col.f32.tf32.tf32.f32 "
        "{%0,%1,%2,%3}, {%4,%5,%6,%7}, {%8,%9}, {%0,%1,%2,%3};"
        : "+f"(d[0]), "+f"(d[1]), "+f"(d[2]), "+f"(d[3])
        : "r"(a[0]), "r"(a[1]), "r"(a[2]), "r"(a[3]), "r"(b0), "r"(b1));
}

// ---------------- router ----------------
__global__ void zero_cnt_kernel() {
    if (threadIdx.x < NE) d_cnt[threadIdx.x] = 0;
}

__global__ void zero_out_kernel(float4* __restrict__ out, int n4) {
    int stride = gridDim.x * blockDim.x;
    float4 z = make_float4(0.f, 0.f, 0.f, 0.f);
    for (int i = blockIdx.x * blockDim.x + threadIdx.x; i < n4; i += stride)
        out[i] = z;
}

__global__ void router_kernel(const float* __restrict__ x,
                              const float* __restrict__ gw,
                              const float* __restrict__ bias) {
    __shared__ float sx[HD];
    __shared__ float sc[NE];
    int t = blockIdx.x;
    const float4* xr = (const float4*)(x + (size_t)t * HD);
    for (int i = threadIdx.x; i < HD / 4; i += blockDim.x)
        ((float4*)sx)[i] = xr[i];
    __syncthreads();

    int warp = threadIdx.x >> 5, lane = threadIdx.x & 31;
    int nwarp = blockDim.x >> 5;
    for (int e = warp; e < NE; e += nwarp) {
        const float* w = gw + (size_t)e * HD;
        float s = 0.f;
        for (int i = lane; i < HD; i += 32) s = fmaf(sx[i], w[i], s);
        #pragma unroll
        for (int o = 16; o > 0; o >>= 1) s += __shfl_xor_sync(0xffffffffu, s, o);
        if (lane == 0) sc[e] = 1.f / (1.f + expf(-s)) + bias[e];
    }
    __syncthreads();

    if (threadIdx.x == 0) {
        float v[NE];
        #pragma unroll
        for (int e = 0; e < NE; e++) v[e] = sc[e];
        int idx[NK]; float wv[NK]; float sum = 0.f;
        #pragma unroll
        for (int k = 0; k < NK; k++) {
            int bi = 0; float bv = -1e30f;
            #pragma unroll
            for (int e = 0; e < NE; e++) if (v[e] > bv) { bv = v[e]; bi = e; }
            idx[k] = bi; wv[k] = bv; v[bi] = -1e30f; sum += bv;
        }
        float inv = 1.f / (sum + 1e-20f);
        #pragma unroll
        for (int k = 0; k < NK; k++) {
            int e = idx[k];
            int pos = atomicAdd(&d_cnt[e], 1);
            d_tok[e * TMAX + pos] = t;
            d_wgt[e * TMAX + pos] = wv[k] * inv;
        }
    }
}

// ============ shared GEMM core (device inline) ============
// C[M,N] = A[M,K] * B[N,K]^T.
// Both operands stream raw via cp.async; tf32 RNA rounding is applied to the
// fragment registers after ldmatrix (CVTA for A; B always).
// GATHER: A rows indirected through tok. ATOMIC: atomicAdd epilogue
// (SCAT: rows scattered via tok, else direct).
template<int GATHER, int ATOMIC, int SCAT, int CVTA>
__device__ __forceinline__ void gemm_core(
    const float* __restrict__ A, const float* __restrict__ B,
    float* __restrict__ C, const int* __restrict__ tok,
    int M, int K, int N, int by, int bx)
{
    extern __shared__ float smem[];
    uint32_t sbase = smem_u32(smem);

    int tid  = threadIdx.x;
    int lane = tid & 31;
    int warp = tid >> 5;
    int wm   = warp & 1;
    int wn   = warp >> 1;

    int lq = (tid & 7) * 4;
    int lr = tid >> 3;
    const float* aP[4];
    const float* bP[4];
    #pragma unroll
    for (int i = 0; i < 4; i++) {
        int r = by * BM + i * 32 + lr;
        int src;
        if (GATHER) src = (r < M) ? tok[r] : tok[0];
        else        src = (r < M) ? r : (M - 1);
        aP[i] = A + (size_t)src * K + lq;
        bP[i] = B + (size_t)(bx * BN + i * 32 + lr) * K + lq;
    }
    uint32_t dOffA = (uint32_t)((lr * LSTR + lq) * 4);
    uint32_t dOffB = dOffA + (uint32_t)(SM_A_FLOATS * 4);

    uint32_t aAddr[4];
    #pragma unroll
    for (int i = 0; i < 4; i++) {
        int row = wm * 64 + i * 16 + (lane & 15);
        int col = (lane >> 4) << 2;
        aAddr[i] = sbase + (uint32_t)((row * LSTR + col) << 2);
    }
    uint32_t bAddr[2];
    #pragma unroll
    for (int p = 0; p < 2; p++) {
        int nrow = wn * 32 + p * 16 + ((lane >> 4) << 3) + (lane & 7);
        int col  = ((lane >> 3) & 1) << 2;
        bAddr[p] = sbase + (uint32_t)(SM_A_FLOATS * 4) +
                   (uint32_t)((nrow * LSTR + col) << 2);
    }

    float acc[4][4][4];
    #pragma unroll
    for (int i = 0; i < 4; i++)
        #pragma unroll
        for (int j = 0; j < 4; j++)
            #pragma unroll
            for (int q = 0; q < 4; q++) acc[i][j][q] = 0.f;

    int NT = K / BKT;

    auto load_chunk = [&](int c) {
        uint32_t sb = sbase + (uint32_t)(c & 1) * STAGE_BYTES;
        int k0 = c * BKT;
        #pragma unroll
        for (int i = 0; i < 4; i++) {
            CPA16(sb + dOffA + (uint32_t)(i * 32 * LSTR * 4), aP[i] + k0);
            CPA16(sb + dOffB + (uint32_t)(i * 32 * LSTR * 4), bP[i] + k0);
        }
        CPA_COMMIT();
    };

    load_chunk(0);

    for (int s = 0; s < NT; s++) {
        CPA_WAIT(0);
        __syncthreads();      // stage s visible; all warps done reading s-1
                              // (its buffer (s+1)&1 is now safe to refill)

        if (s + 1 < NT) load_chunk(s + 1);   // overlaps compute of s

        uint32_t stOff = (uint32_t)(s & 1) * STAGE_BYTES;

        #pragma unroll
        for (int ks = 0; ks < BKT; ks += 8) {
            uint32_t kOff = stOff + (uint32_t)(ks << 2);
            unsigned a[4][4];
            #pragma unroll
            for (int i = 0; i < 4; i++) {
                LDSM4(a[i][0], a[i][1], a[i][2], a[i][3], aAddr[i] + kOff);
                if (CVTA) {
                    #pragma unroll
                    for (int q = 0; q < 4; q++) a[i][q] = cvt_bits(a[i][q]);
                }
            }
            unsigned b[2][4];
            #pragma unroll
            for (int p = 0; p < 2; p++) {
                LDSM4(b[p][0], b[p][1], b[p][2], b[p][3], bAddr[p] + kOff);
                #pragma unroll
                for (int q = 0; q < 4; q++) b[p][q] = cvt_bits(b[p][q]);
            }
            #pragma unroll
            for (int j = 0; j < 4; j++) {
                unsigned b0 = b[j >> 1][(j & 1) * 2];
                unsigned b1 = b[j >> 1][(j & 1) * 2 + 1];
                #pragma unroll
                for (int i = 0; i < 4; i++)
                    mma_tf32(acc[i][j], a[i], b0, b1);
            }
        }
    }

    // epilogue
    #pragma unroll
    for (int i = 0; i < 4; i++) {
        int r0 = by * BM + wm * 64 + i * 16 + (lane >> 2);
        #pragma unroll
        for (int j = 0; j < 4; j++) {
            int c0 = bx * BN + wn * 32 + j * 8 + 2 * (lane & 3);
            if (ATOMIC) {
                if (r0 < M) {
                    int tr = SCAT ? tok[r0] : r0;
                    atomicAdd(C + (size_t)tr * N + c0,     acc[i][j][0]);
                    atomicAdd(C + (size_t)tr * N + c0 + 1, acc[i][j][1]);
                }
                if (r0 + 8 < M) {
                    int tr = SCAT ? tok[r0 + 8] : (r0 + 8);
                    atomicAdd(C + (size_t)tr * N + c0,     acc[i][j][2]);
                    atomicAdd(C + (size_t)tr * N + c0 + 1, acc[i][j][3]);
                }
            } else {
                if (r0 < M) {
                    *(float2*)(C + (size_t)r0 * N + c0) =
                        make_float2(acc[i][j][0], acc[i][j][1]);
                }
                if (r0 + 8 < M) {
                    *(float2*)(C + (size_t)(r0 + 8) * N + c0) =
                        make_float2(acc[i][j][2], acc[i][j][3]);
                }
            }
        }
    }
}

// ---------------- fused gate+up GEMM launch ----------------
// grid (32, 32, NE+1): x: [0,16) gate / [16,32) up; z<NE routed, z==NE shared.
__global__ __launch_bounds__(256, 2)
void gemm_gu(const float* __restrict__ x,
             const float* __restrict__ Wg, const float* __restrict__ Wu,
             const float* __restrict__ Sg, const float* __restrict__ Su,
             int Tn) {
    int e  = blockIdx.z;
    int up = blockIdx.x >> 4;
    int bx = blockIdx.x & 15;
    int by = blockIdx.y;

    if (e < NE) {
        int M = d_cnt[e];
        if (by * BM >= M) return;
        const float* B = (up ? Wu : Wg) + (size_t)e * IS * HD;
        float* C = (up ? d_bufU : d_bufG) + (size_t)e * TMAX * IS;
        gemm_core<1, 0, 0, 1>(x, B, C, d_tok + e * TMAX, M, HD, IS, by, bx);
    } else {
        if (by * BM >= Tn) return;
        const float* B = up ? Su : Sg;
        float* C = up ? d_sU : d_sG;
        gemm_core<0, 0, 0, 1>(x, B, C, nullptr, Tn, HD, SIW, by, bx);
    }
}

// ---------------- fused down GEMM launch (out zero-initialized) ----------------
// grid (32, 32, NE+1): z<NE routed (scatter-atomic), z==NE shared (direct-atomic).
__global__ __launch_bounds__(256, 2)
void gemm_down(const float* __restrict__ Wd, const float* __restrict__ Sd,
               float* __restrict__ out, int Tn) {
    int e  = blockIdx.z;
    int bx = blockIdx.x;
    int by = blockIdx.y;

    if (e < NE) {
        int M = d_cnt[e];
        if (by * BM >= M) return;
        gemm_core<0, 1, 1, 0>(d_bufG + (size_t)e * TMAX * IS,
                              Wd + (size_t)e * HD * IS,
                              out, d_tok + e * TMAX, M, IS, HD, by, bx);
    } else {
        if (by * BM >= Tn) return;
        gemm_core<0, 1, 0, 0>(d_sG, Sd, out, nullptr, Tn, SIW, HD, by, bx);
    }
}

// ---------------- fused activation (routed z<NE, shared z==NE) ----------------
__device__ __forceinline__ float silu_f(float v) {
    return v / (1.f + expf(-v));
}

__global__ void act_kernel() {
    int e   = blockIdx.y;
    int row = blockIdx.x;
    float w;
    float4 *g4;
    const float4 *u4;
    if (e < NE) {
        if (row >= d_cnt[e]) return;
        w = d_wgt[e * TMAX + row];
        size_t base = ((size_t)e * TMAX + row) * IS;
        g4 = (float4*)(d_bufG + base);
        u4 = (const float4*)(d_bufU + base);
    } else {
        w = 1.f;
        size_t base = (size_t)row * SIW;
        g4 = (float4*)(d_sG + base);
        u4 = (const float4*)(d_sU + base);
    }
    for (int i = threadIdx.x; i < IS / 4; i += blockDim.x) {
        float4 g = g4[i], u = u4[i], z;
        z.x = rndf(silu_f(g.x) * u.x * w);
        z.y = rndf(silu_f(g.y) * u.y * w);
        z.z = rndf(silu_f(g.z) * u.z * w);
        z.w = rndf(silu_f(g.w) * u.w * w);
        g4[i] = z;
    }
}

// ---------------- launch ----------------
extern "C" void kernel_launch(void* const* d_in, const int* in_sizes, int n_in,
                              void* d_out, int out_size) {
    const float* x    = (const float*)d_in[0];
    const float* gw   = (const float*)d_in[1];
    const float* bias = (const float*)d_in[2];
    const float* Wg   = (const float*)d_in[3];
    const float* Wu   = (const float*)d_in[4];
    const float* Wd   = (const float*)d_in[5];
    const float* Sg   = (const float*)d_in[6];
    const float* Su   = (const float*)d_in[7];
    const float* Sd   = (const float*)d_in[8];
    float* out = (float*)d_out;

    int Tn = in_sizes[0] / HD;            // 4096 tokens

    static int smem_set = 0;
    if (!smem_set) {
        cudaFuncSetAttribute(gemm_gu,   cudaFuncAttributeMaxDynamicSharedMemorySize, DSMEM_BYTES);
        cudaFuncSetAttribute(gemm_down, cudaFuncAttributeMaxDynamicSharedMemorySize, DSMEM_BYTES);
        smem_set = 1;
    }

    zero_cnt_kernel<<<1, 32>>>();
    zero_out_kernel<<<1024, 256>>>((float4*)out, (int)((size_t)Tn * HD / 4));
    router_kernel<<<Tn, 128>>>(x, gw, bias);

    // all four gate/up GEMMs (16 routed experts + shared) in one launch
    gemm_gu<<<dim3(32, 32, NE + 1), 256, DSMEM_BYTES>>>(x, Wg, Wu, Sg, Su, Tn);

    // fused activation (routed + shared)
    act_kernel<<<dim3(Tn, NE + 1), 256>>>();

    // all down GEMMs (16 routed + shared) in one launch, atomicAdd into out
    gemm_down<<<dim3(HD / BN, 32, NE + 1), 256, DSMEM_BYTES>>>(Wd, Sd, out, Tn);

    (void)n_in; (void)out_size;
}

// round 14
// speedup vs baseline: 1.0997x; 1.0997x over previous
#include <cuda_runtime.h>
#include <math.h>
#include <stdint.h>

// Problem constants
#define HD   4096
#define IS   2048
#define NE   16
#define NK   4
#define SIW  2048
#define TMAX 4096

// GEMM tile: CTA 128x128, 8 warps (2M x 4N), warp tile 64x32, K-chunk 32
#define BM   128
#define BN   128
#define BKT  32
#define LSTR 36                              // padded row stride (floats)
#define SM_A_FLOATS (BM * LSTR)              // 4608
#define SM_STAGE    (2 * SM_A_FLOATS)        // A + B per stage = 9216 floats
#define STAGE_BYTES (SM_STAGE * 4)           // 36864
#define DSMEM_BYTES (2 * STAGE_BYTES)        // 73728

// ---------------- static device scratch ----------------
__device__ int   d_cnt[NE];
__device__ int   d_tok[NE * TMAX];
__device__ float d_wgt[NE * TMAX];
__device__ float d_bufG[(size_t)NE * TMAX * IS];   // routed gate proj -> z (rounded)
__device__ float d_bufU[(size_t)NE * TMAX * IS];   // routed up proj
__device__ float d_sG[(size_t)TMAX * SIW];         // shared gate -> z (rounded)
__device__ float d_sU[(size_t)TMAX * SIW];         // shared up
__device__ float d_xr[(size_t)TMAX * HD];          // tf32-rounded x

// ---------------- helpers ----------------
__device__ __forceinline__ uint32_t smem_u32(const void* p) {
    uint32_t a;
    asm("{ .reg .u64 t; cvta.to.shared.u64 t, %1; cvt.u32.u64 %0, t; }" : "=r"(a) : "l"(p));
    return a;
}
__device__ __forceinline__ unsigned f2tf32(float f) {
    unsigned r;
    asm("cvt.rna.tf32.f32 %0, %1;" : "=r"(r) : "f"(f));
    return r;
}
__device__ __forceinline__ float rndf(float v) {
    return __uint_as_float(f2tf32(v));
}
#define CPA16(dst, src) \
    asm volatile("cp.async.cg.shared.global [%0], [%1], 16;" :: "r"(dst), "l"(src))
#define CPA_COMMIT() asm volatile("cp.async.commit_group;")
#define CPA_WAIT(n)  asm volatile("cp.async.wait_group %0;" :: "n"(n))

#define LDSM4(r0, r1, r2, r3, addr) \
    asm volatile("ldmatrix.sync.aligned.m8n8.x4.shared.b16 {%0,%1,%2,%3}, [%4];" \
                 : "=r"(r0), "=r"(r1), "=r"(r2), "=r"(r3) : "r"(addr))

__device__ __forceinline__ void mma_tf32(float* d, const unsigned* a, unsigned b0, unsigned b1) {
    asm volatile(
        "mma.sync.aligned.m16n8k8.row.col.f32.tf32.tf32.f32 "
        "{%0,%1,%2,%3}, {%4,%5,%6,%7}, {%8,%9}, {%0,%1,%2,%3};"
        : "+f"(d[0]), "+f"(d[1]), "+f"(d[2]), "+f"(d[3])
        : "r"(a[0]), "r"(a[1]), "r"(a[2]), "r"(a[3]), "r"(b0), "r"(b1));
}

// ---------------- small kernels ----------------
__global__ void zero_cnt_kernel() {
    if (threadIdx.x < NE) d_cnt[threadIdx.x] = 0;
}

__global__ void zero_out_kernel(float4* __restrict__ out, int n4) {
    int stride = gridDim.x * blockDim.x;
    float4 z = make_float4(0.f, 0.f, 0.f, 0.f);
    for (int i = blockIdx.x * blockDim.x + threadIdx.x; i < n4; i += stride)
        out[i] = z;
}

__global__ void router_kernel(const float* __restrict__ x,
                              const float* __restrict__ gw,
                              const float* __restrict__ bias) {
    __shared__ float sx[HD];
    __shared__ float sc[NE];
    int t = blockIdx.x;
    const float4* xr = (const float4*)(x + (size_t)t * HD);
    for (int i = threadIdx.x; i < HD / 4; i += blockDim.x)
        ((float4*)sx)[i] = xr[i];
    __syncthreads();

    int warp = threadIdx.x >> 5, lane = threadIdx.x & 31;
    int nwarp = blockDim.x >> 5;
    for (int e = warp; e < NE; e += nwarp) {
        const float* w = gw + (size_t)e * HD;
        float s = 0.f;
        for (int i = lane; i < HD; i += 32) s = fmaf(sx[i], w[i], s);
        #pragma unroll
        for (int o = 16; o > 0; o >>= 1) s += __shfl_xor_sync(0xffffffffu, s, o);
        if (lane == 0) sc[e] = 1.f / (1.f + expf(-s)) + bias[e];
    }
    __syncthreads();

    if (threadIdx.x == 0) {
        float v[NE];
        #pragma unroll
        for (int e = 0; e < NE; e++) v[e] = sc[e];
        int idx[NK]; float wv[NK]; float sum = 0.f;
        #pragma unroll
        for (int k = 0; k < NK; k++) {
            int bi = 0; float bv = -1e30f;
            #pragma unroll
            for (int e = 0; e < NE; e++) if (v[e] > bv) { bv = v[e]; bi = e; }
            idx[k] = bi; wv[k] = bv; v[bi] = -1e30f; sum += bv;
        }
        float inv = 1.f / (sum + 1e-20f);
        #pragma unroll
        for (int k = 0; k < NK; k++) {
            int e = idx[k];
            int pos = atomicAdd(&d_cnt[e], 1);
            d_tok[e * TMAX + pos] = t;
            d_wgt[e * TMAX + pos] = wv[k] * inv;
        }
    }
}

// ---------------- tf32 pre-rounding (x only) ----------------
__global__ void round_kernel(const float4* __restrict__ in, int n4) {
    float4* out = (float4*)d_xr;
    int stride = gridDim.x * blockDim.x;
    for (int i = blockIdx.x * blockDim.x + threadIdx.x; i < n4; i += stride) {
        float4 v = in[i];
        float4 o;
        o.x = rndf(v.x); o.y = rndf(v.y); o.z = rndf(v.z); o.w = rndf(v.w);
        out[i] = o;
    }
}

// ============ shared GEMM core (device inline) — R12 mainloop ============
// C[M,N] = A[M,K] * B[N,K]^T.
// A: tf32-pre-rounded buffer, streamed via cp.async.
// B: raw fp32 weights: LDG -> cvt.rna (once per element) -> STS.
// Inner loop: pure LDSM + HMMA.
// GATHER: A rows indirected via tok. ATOMIC: atomicAdd epilogue
// (SCAT: epilogue rows scattered through tok).
template<int GATHER, int ATOMIC, int SCAT>
__device__ __forceinline__ void gemm_core(
    const float* __restrict__ A, const float* __restrict__ B,
    float* __restrict__ C, const int* __restrict__ tok,
    int M, int K, int N, int by, int bx)
{
    extern __shared__ float smem[];
    uint32_t sbase = smem_u32(smem);

    int tid  = threadIdx.x;
    int lane = tid & 31;
    int warp = tid >> 5;
    int wm   = warp & 1;
    int wn   = warp >> 1;

    int lq = (tid & 7) * 4;
    int lr = tid >> 3;
    const float* aP[4];
    const float* bP[4];
    #pragma unroll
    for (int i = 0; i < 4; i++) {
        int r = by * BM + i * 32 + lr;
        int src;
        if (GATHER) src = (r < M) ? tok[r] : tok[0];
        else        src = (r < M) ? r : (M - 1);
        aP[i] = A + (size_t)src * K + lq;
        bP[i] = B + (size_t)(bx * BN + i * 32 + lr) * K + lq;
    }
    uint32_t dOffA = (uint32_t)((lr * LSTR + lq) * 4);
    int      sOffB = SM_A_FLOATS + lr * LSTR + lq;

    uint32_t aAddr[4];
    #pragma unroll
    for (int i = 0; i < 4; i++) {
        int row = wm * 64 + i * 16 + (lane & 15);
        int col = (lane >> 4) << 2;
        aAddr[i] = sbase + (uint32_t)((row * LSTR + col) << 2);
    }
    uint32_t bAddr[2];
    #pragma unroll
    for (int p = 0; p < 2; p++) {
        int nrow = wn * 32 + p * 16 + ((lane >> 4) << 3) + (lane & 7);
        int col  = ((lane >> 3) & 1) << 2;
        bAddr[p] = sbase + (uint32_t)(SM_A_FLOATS * 4) +
                   (uint32_t)((nrow * LSTR + col) << 2);
    }

    float acc[4][4][4];
    #pragma unroll
    for (int i = 0; i < 4; i++)
        #pragma unroll
        for (int j = 0; j < 4; j++)
            #pragma unroll
            for (int q = 0; q < 4; q++) acc[i][j][q] = 0.f;

    int NT = K / BKT;
    float4 bReg[4];

    auto load_chunkA = [&](int c) {
        uint32_t sb = sbase + (uint32_t)(c & 1) * STAGE_BYTES;
        int k0 = c * BKT;
        #pragma unroll
        for (int i = 0; i < 4; i++)
            CPA16(sb + dOffA + (uint32_t)(i * 32 * LSTR * 4), aP[i] + k0);
        CPA_COMMIT();
    };
    auto ldg_B = [&](int c) {
        int k0 = c * BKT;
        #pragma unroll
        for (int i = 0; i < 4; i++)
            bReg[i] = *(const float4*)(bP[i] + k0);
    };
    auto sts_B = [&](int c) {
        float* st = smem + (c & 1) * SM_STAGE + sOffB;
        #pragma unroll
        for (int i = 0; i < 4; i++) {
            float4 v = bReg[i];
            float4 o;
            o.x = rndf(v.x); o.y = rndf(v.y); o.z = rndf(v.z); o.w = rndf(v.w);
            *(float4*)(st + i * 32 * LSTR) = o;
        }
    };

    load_chunkA(0);
    ldg_B(0);
    sts_B(0);

    for (int s = 0; s < NT; s++) {
        CPA_WAIT(0);
        __syncthreads();      // stage s fully visible; all warps done with s-1

        if (s + 1 < NT) {
            ldg_B(s + 1);     // long-latency LDG issued before compute
            load_chunkA(s + 1);
        }

        uint32_t stOff = (uint32_t)(s & 1) * STAGE_BYTES;

        #pragma unroll
        for (int ks = 0; ks < BKT; ks += 8) {
            uint32_t kOff = stOff + (uint32_t)(ks << 2);
            unsigned a[4][4];
            #pragma unroll
            for (int i = 0; i < 4; i++)
                LDSM4(a[i][0], a[i][1], a[i][2], a[i][3], aAddr[i] + kOff);
            unsigned b[2][4];
            #pragma unroll
            for (int p = 0; p < 2; p++)
                LDSM4(b[p][0], b[p][1], b[p][2], b[p][3], bAddr[p] + kOff);
            #pragma unroll
            for (int j = 0; j < 4; j++) {
                unsigned b0 = b[j >> 1][(j & 1) * 2];
                unsigned b1 = b[j >> 1][(j & 1) * 2 + 1];
                #pragma unroll
                for (int i = 0; i < 4; i++)
                    mma_tf32(acc[i][j], a[i], b0, b1);
            }
        }

        if (s + 1 < NT) sts_B(s + 1);   // stage (s+1)&1: not read until after
                                        // next iteration's barrier
    }

    // epilogue
    #pragma unroll
    for (int i = 0; i < 4; i++) {
        int r0 = by * BM + wm * 64 + i * 16 + (lane >> 2);
        #pragma unroll
        for (int j = 0; j < 4; j++) {
            int c0 = bx * BN + wn * 32 + j * 8 + 2 * (lane & 3);
            if (ATOMIC) {
                if (r0 < M) {
                    int tr = SCAT ? tok[r0] : r0;
                    atomicAdd(C + (size_t)tr * N + c0,     acc[i][j][0]);
                    atomicAdd(C + (size_t)tr * N + c0 + 1, acc[i][j][1]);
                }
                if (r0 + 8 < M) {
                    int tr = SCAT ? tok[r0 + 8] : (r0 + 8);
                    atomicAdd(C + (size_t)tr * N + c0,     acc[i][j][2]);
                    atomicAdd(C + (size_t)tr * N + c0 + 1, acc[i][j][3]);
                }
            } else {
                if (r0 < M) {
                    *(float2*)(C + (size_t)r0 * N + c0) =
                        make_float2(acc[i][j][0], acc[i][j][1]);
                }
                if (r0 + 8 < M) {
                    *(float2*)(C + (size_t)(r0 + 8) * N + c0) =
                        make_float2(acc[i][j][2], acc[i][j][3]);
                }
            }
        }
    }
}

// ---------------- fused gate+up GEMM launch ----------------
// grid (32, 32, NE+1): x: [0,16) gate / [16,32) up; z<NE routed, z==NE shared.
__global__ __launch_bounds__(256, 2)
void gemm_gu(const float* __restrict__ Wg, const float* __restrict__ Wu,
             const float* __restrict__ Sg, const float* __restrict__ Su,
             int Tn) {
    int e  = blockIdx.z;
    int up = blockIdx.x >> 4;
    int bx = blockIdx.x & 15;
    int by = blockIdx.y;

    if (e < NE) {
        int M = d_cnt[e];
        if (by * BM >= M) return;
        const float* B = (up ? Wu : Wg) + (size_t)e * IS * HD;
        float* C = (up ? d_bufU : d_bufG) + (size_t)e * TMAX * IS;
        gemm_core<1, 0, 0>(d_xr, B, C, d_tok + e * TMAX, M, HD, IS, by, bx);
    } else {
        if (by * BM >= Tn) return;
        const float* B = up ? Su : Sg;
        float* C = up ? d_sU : d_sG;
        gemm_core<0, 0, 0>(d_xr, B, C, nullptr, Tn, HD, SIW, by, bx);
    }
}

// ---------------- fused down GEMM launch (out zero-initialized) ----------------
// grid (32, 32, NE+1): z<NE routed (scatter-atomic), z==NE shared (direct-atomic).
__global__ __launch_bounds__(256, 2)
void gemm_down(const float* __restrict__ Wd, const float* __restrict__ Sd,
               float* __restrict__ out, int Tn) {
    int e  = blockIdx.z;
    int bx = blockIdx.x;
    int by = blockIdx.y;

    if (e < NE) {
        int M = d_cnt[e];
        if (by * BM >= M) return;
        gemm_core<0, 1, 1>(d_bufG + (size_t)e * TMAX * IS,
                           Wd + (size_t)e * HD * IS,
                           out, d_tok + e * TMAX, M, IS, HD, by, bx);
    } else {
        if (by * BM >= Tn) return;
        gemm_core<0, 1, 0>(d_sG, Sd, out, nullptr, Tn, SIW, HD, by, bx);
    }
}

// ---------------- fused activation (routed z<NE, shared z==NE) ----------------
__device__ __forceinline__ float silu_f(float v) {
    return v / (1.f + expf(-v));
}

__global__ void act_kernel() {
    int e   = blockIdx.y;
    int row = blockIdx.x;
    float w;
    float4 *g4;
    const float4 *u4;
    if (e < NE) {
        if (row >= d_cnt[e]) return;
        w = d_wgt[e * TMAX + row];
        size_t base = ((size_t)e * TMAX + row) * IS;
        g4 = (float4*)(d_bufG + base);
        u4 = (const float4*)(d_bufU + base);
    } else {
        w = 1.f;
        size_t base = (size_t)row * SIW;
        g4 = (float4*)(d_sG + base);
        u4 = (const float4*)(d_sU + base);
    }
    for (int i = threadIdx.x; i < IS / 4; i += blockDim.x) {
        float4 g = g4[i], u = u4[i], z;
        z.x = rndf(silu_f(g.x) * u.x * w);
        z.y = rndf(silu_f(g.y) * u.y * w);
        z.z = rndf(silu_f(g.z) * u.z * w);
        z.w = rndf(silu_f(g.w) * u.w * w);
        g4[i] = z;
    }
}

// ---------------- launch ----------------
extern "C" void kernel_launch(void* const* d_in, const int* in_sizes, int n_in,
                              void* d_out, int out_size) {
    const float* x    = (const float*)d_in[0];
    const float* gw   = (const float*)d_in[1];
    const float* bias = (const float*)d_in[2];
    const float* Wg   = (const float*)d_in[3];
    const float* Wu   = (const float*)d_in[4];
    const float* Wd   = (const float*)d_in[5];
    const float* Sg   = (const float*)d_in[6];
    const float* Su   = (const float*)d_in[7];
    const float* Sd   = (const float*)d_in[8];
    float* out = (float*)d_out;

    int Tn = in_sizes[0] / HD;            // 4096 tokens

    static int smem_set = 0;
    if (!smem_set) {
        cudaFuncSetAttribute(gemm_gu,   cudaFuncAttributeMaxDynamicSharedMemorySize, DSMEM_BYTES);
        cudaFuncSetAttribute(gemm_down, cudaFuncAttributeMaxDynamicSharedMemorySize, DSMEM_BYTES);
        smem_set = 1;
    }

    zero_cnt_kernel<<<1, 32>>>();
    zero_out_kernel<<<1024, 256>>>((float4*)out, (int)((size_t)Tn * HD / 4));
    router_kernel<<<Tn, 128>>>(x, gw, bias);
    round_kernel<<<2048, 256>>>((const float4*)x, (int)((size_t)Tn * HD / 4));

    // all four gate/up GEMMs (16 routed experts + shared) in one launch
    gemm_gu<<<dim3(32, 32, NE + 1), 256, DSMEM_BYTES>>>(Wg, Wu, Sg, Su, Tn);

    // fused activation (routed + shared)
    act_kernel<<<dim3(Tn, NE + 1), 256>>>();

    // all down GEMMs (16 routed + shared) in one launch, atomicAdd into out
    gemm_down<<<dim3(HD / BN, 32, NE + 1), 256, DSMEM_BYTES>>>(Wd, Sd, out, Tn);

    (void)n_in; (void)out_size;
}

// round 15
// speedup vs baseline: 1.1037x; 1.0036x over previous
#include <cuda_runtime.h>
#include <math.h>
#include <stdint.h>

// Problem constants
#define HD   4096
#define IS   2048
#define NE   16
#define NK   4
#define SIW  2048
#define TMAX 4096

// GEMM tile: CTA 128x128, 8 warps (2M x 4N), warp tile 64x32, K-chunk 32
#define BM   128
#define BN   128
#define BKT  32
#define LSTR 36                              // padded row stride (floats)
#define SM_A_FLOATS (BM * LSTR)              // 4608
#define SM_STAGE    (2 * SM_A_FLOATS)        // A + B per stage = 9216 floats
#define STAGE_BYTES (SM_STAGE * 4)           // 36864
#define DSMEM_BYTES (2 * STAGE_BYTES)        // 73728
#define XST  66                              // exchange smem row stride (floats)

// ---------------- static device scratch ----------------
__device__ int   d_cnt[NE];
__device__ int   d_tok[NE * TMAX];
__device__ float d_wgt[NE * TMAX];
__device__ float d_bufZ[(size_t)NE * TMAX * IS];   // routed z (tf32-rounded)
__device__ float d_sZ[(size_t)TMAX * SIW];         // shared z (tf32-rounded)
__device__ float d_xr[(size_t)TMAX * HD];          // tf32-rounded x

// ---------------- helpers ----------------
__device__ __forceinline__ uint32_t smem_u32(const void* p) {
    uint32_t a;
    asm("{ .reg .u64 t; cvta.to.shared.u64 t, %1; cvt.u32.u64 %0, t; }" : "=r"(a) : "l"(p));
    return a;
}
__device__ __forceinline__ unsigned f2tf32(float f) {
    unsigned r;
    asm("cvt.rna.tf32.f32 %0, %1;" : "=r"(r) : "f"(f));
    return r;
}
__device__ __forceinline__ float rndf(float v) {
    return __uint_as_float(f2tf32(v));
}
__device__ __forceinline__ float silu_f(float v) {
    return v / (1.f + expf(-v));
}
#define CPA16(dst, src) \
    asm volatile("cp.async.cg.shared.global [%0], [%1], 16;" :: "r"(dst), "l"(src))
#define CPA_COMMIT() asm volatile("cp.async.commit_group;")
#define CPA_WAIT(n)  asm volatile("cp.async.wait_group %0;" :: "n"(n))

#define LDSM4(r0, r1, r2, r3, addr) \
    asm volatile("ldmatrix.sync.aligned.m8n8.x4.shared.b16 {%0,%1,%2,%3}, [%4];" \
                 : "=r"(r0), "=r"(r1), "=r"(r2), "=r"(r3) : "r"(addr))

__device__ __forceinline__ void mma_tf32(float* d, const unsigned* a, unsigned b0, unsigned b1) {
    asm volatile(
        "mma.sync.aligned.m16n8k8.row.col.f32.tf32.tf32.f32 "
        "{%0,%1,%2,%3}, {%4,%5,%6,%7}, {%8,%9}, {%0,%1,%2,%3};"
        : "+f"(d[0]), "+f"(d[1]), "+f"(d[2]), "+f"(d[3])
        : "r"(a[0]), "r"(a[1]), "r"(a[2]), "r"(a[3]), "r"(b0), "r"(b1));
}

// ---------------- small kernels ----------------
__global__ void zero_cnt_kernel() {
    if (threadIdx.x < NE) d_cnt[threadIdx.x] = 0;
}

__global__ void router_kernel(const float* __restrict__ x,
                              const float* __restrict__ gw,
                              const float* __restrict__ bias) {
    __shared__ float sx[HD];
    __shared__ float sc[NE];
    int t = blockIdx.x;
    const float4* xr = (const float4*)(x + (size_t)t * HD);
    for (int i = threadIdx.x; i < HD / 4; i += blockDim.x)
        ((float4*)sx)[i] = xr[i];
    __syncthreads();

    int warp = threadIdx.x >> 5, lane = threadIdx.x & 31;
    int nwarp = blockDim.x >> 5;
    for (int e = warp; e < NE; e += nwarp) {
        const float* w = gw + (size_t)e * HD;
        float s = 0.f;
        for (int i = lane; i < HD; i += 32) s = fmaf(sx[i], w[i], s);
        #pragma unroll
        for (int o = 16; o > 0; o >>= 1) s += __shfl_xor_sync(0xffffffffu, s, o);
        if (lane == 0) sc[e] = 1.f / (1.f + expf(-s)) + bias[e];
    }
    __syncthreads();

    if (threadIdx.x == 0) {
        float v[NE];
        #pragma unroll
        for (int e = 0; e < NE; e++) v[e] = sc[e];
        int idx[NK]; float wv[NK]; float sum = 0.f;
        #pragma unroll
        for (int k = 0; k < NK; k++) {
            int bi = 0; float bv = -1e30f;
            #pragma unroll
            for (int e = 0; e < NE; e++) if (v[e] > bv) { bv = v[e]; bi = e; }
            idx[k] = bi; wv[k] = bv; v[bi] = -1e30f; sum += bv;
        }
        float inv = 1.f / (sum + 1e-20f);
        #pragma unroll
        for (int k = 0; k < NK; k++) {
            int e = idx[k];
            int pos = atomicAdd(&d_cnt[e], 1);
            d_tok[e * TMAX + pos] = t;
            d_wgt[e * TMAX + pos] = wv[k] * inv;
        }
    }
}

// ---------------- tf32 pre-rounding (x only) ----------------
__global__ void round_kernel(const float4* __restrict__ in, int n4) {
    float4* out = (float4*)d_xr;
    int stride = gridDim.x * blockDim.x;
    for (int i = blockIdx.x * blockDim.x + threadIdx.x; i < n4; i += stride) {
        float4 v = in[i];
        float4 o;
        o.x = rndf(v.x); o.y = rndf(v.y); o.z = rndf(v.z); o.w = rndf(v.w);
        out[i] = o;
    }
}

// ============ fused gate+up+act core ============
// One CTA computes a 128x64 z-tile: B smem rows 0-63 = Wg rows (gate),
// rows 64-127 = Wu rows (up), same 64 output columns. Warps wn<2 hold g,
// wn>=2 hold u; epilogue exchanges u through smem, g-warps emit
// z = rndf(silu(g)*u*w).
template<int GATHER>
__device__ __forceinline__ void guz_core(
    const float* __restrict__ A,
    const float* __restrict__ Bg, const float* __restrict__ Bu,
    float* __restrict__ C, const int* __restrict__ tok,
    const float* __restrict__ wgt,
    int M, int K, int N, int by, int bx)
{
    extern __shared__ float smem[];
    uint32_t sbase = smem_u32(smem);

    int tid  = threadIdx.x;
    int lane = tid & 31;
    int warp = tid >> 5;
    int wm   = warp & 1;
    int wn   = warp >> 1;

    int lq = (tid & 7) * 4;
    int lr = tid >> 3;
    const float* aP[4];
    const float* bP[4];
    #pragma unroll
    for (int i = 0; i < 4; i++) {
        int r = by * BM + i * 32 + lr;
        int src;
        if (GATHER) src = (r < M) ? tok[r] : tok[0];
        else        src = (r < M) ? r : (M - 1);
        aP[i] = A + (size_t)src * K + lq;
    }
    bP[0] = Bg + (size_t)(bx * 64 + lr)      * K + lq;
    bP[1] = Bg + (size_t)(bx * 64 + 32 + lr) * K + lq;
    bP[2] = Bu + (size_t)(bx * 64 + lr)      * K + lq;
    bP[3] = Bu + (size_t)(bx * 64 + 32 + lr) * K + lq;

    uint32_t dOffA = (uint32_t)((lr * LSTR + lq) * 4);
    int      sOffB = SM_A_FLOATS + lr * LSTR + lq;

    uint32_t aAddr[4];
    #pragma unroll
    for (int i = 0; i < 4; i++) {
        int row = wm * 64 + i * 16 + (lane & 15);
        int col = (lane >> 4) << 2;
        aAddr[i] = sbase + (uint32_t)((row * LSTR + col) << 2);
    }
    uint32_t bAddr[2];
    #pragma unroll
    for (int p = 0; p < 2; p++) {
        int nrow = wn * 32 + p * 16 + ((lane >> 4) << 3) + (lane & 7);
        int col  = ((lane >> 3) & 1) << 2;
        bAddr[p] = sbase + (uint32_t)(SM_A_FLOATS * 4) +
                   (uint32_t)((nrow * LSTR + col) << 2);
    }

    float acc[4][4][4];
    #pragma unroll
    for (int i = 0; i < 4; i++)
        #pragma unroll
        for (int j = 0; j < 4; j++)
            #pragma unroll
            for (int q = 0; q < 4; q++) acc[i][j][q] = 0.f;

    int NT = K / BKT;
    float4 bReg[4];

    auto load_chunkA = [&](int c) {
        uint32_t sb = sbase + (uint32_t)(c & 1) * STAGE_BYTES;
        int k0 = c * BKT;
        #pragma unroll
        for (int i = 0; i < 4; i++)
            CPA16(sb + dOffA + (uint32_t)(i * 32 * LSTR * 4), aP[i] + k0);
        CPA_COMMIT();
    };
    auto ldg_B = [&](int c) {
        int k0 = c * BKT;
        #pragma unroll
        for (int i = 0; i < 4; i++)
            bReg[i] = *(const float4*)(bP[i] + k0);
    };
    auto sts_B = [&](int c) {
        float* st = smem + (c & 1) * SM_STAGE + sOffB;
        #pragma unroll
        for (int i = 0; i < 4; i++) {
            float4 v = bReg[i];
            float4 o;
            o.x = rndf(v.x); o.y = rndf(v.y); o.z = rndf(v.z); o.w = rndf(v.w);
            *(float4*)(st + i * 32 * LSTR) = o;
        }
    };

    load_chunkA(0);
    ldg_B(0);
    sts_B(0);

    for (int s = 0; s < NT; s++) {
        CPA_WAIT(0);
        __syncthreads();

        if (s + 1 < NT) {
            ldg_B(s + 1);
            load_chunkA(s + 1);
        }

        uint32_t stOff = (uint32_t)(s & 1) * STAGE_BYTES;

        #pragma unroll
        for (int ks = 0; ks < BKT; ks += 8) {
            uint32_t kOff = stOff + (uint32_t)(ks << 2);
            unsigned a[4][4];
            #pragma unroll
            for (int i = 0; i < 4; i++)
                LDSM4(a[i][0], a[i][1], a[i][2], a[i][3], aAddr[i] + kOff);
            unsigned b[2][4];
            #pragma unroll
            for (int p = 0; p < 2; p++)
                LDSM4(b[p][0], b[p][1], b[p][2], b[p][3], bAddr[p] + kOff);
            #pragma unroll
            for (int j = 0; j < 4; j++) {
                unsigned b0 = b[j >> 1][(j & 1) * 2];
                unsigned b1 = b[j >> 1][(j & 1) * 2 + 1];
                #pragma unroll
                for (int i = 0; i < 4; i++)
                    mma_tf32(acc[i][j], a[i], b0, b1);
            }
        }

        if (s + 1 < NT) sts_B(s + 1);
    }

    // ---- fused activation epilogue ----
    __syncthreads();                 // all k-loop smem reads done; reuse smem
    if (wn >= 2) {                   // u-warps publish acc
        #pragma unroll
        for (int i = 0; i < 4; i++) {
            int rl = wm * 64 + i * 16 + (lane >> 2);
            #pragma unroll
            for (int j = 0; j < 4; j++) {
                int cl = (wn - 2) * 32 + j * 8 + 2 * (lane & 3);
                *(float2*)&smem[rl * XST + cl] =
                    make_float2(acc[i][j][0], acc[i][j][1]);
                *(float2*)&smem[(rl + 8) * XST + cl] =
                    make_float2(acc[i][j][2], acc[i][j][3]);
            }
        }
    }
    __syncthreads();
    if (wn < 2) {                    // g-warps emit z = rndf(silu(g)*u*w)
        #pragma unroll
        for (int i = 0; i < 4; i++) {
            int rl = wm * 64 + i * 16 + (lane >> 2);
            int r0 = by * BM + rl;
            float w0 = 1.f, w1 = 1.f;
            if (GATHER) {
                if (r0 < M)     w0 = wgt[r0];
                if (r0 + 8 < M) w1 = wgt[r0 + 8];
            }
            #pragma unroll
            for (int j = 0; j < 4; j++) {
                int cl = wn * 32 + j * 8 + 2 * (lane & 3);
                float2 u0 = *(float2*)&smem[rl * XST + cl];
                float2 u1 = *(float2*)&smem[(rl + 8) * XST + cl];
                int c0 = bx * 64 + cl;
                if (r0 < M) {
                    float2 z;
                    z.x = rndf(silu_f(acc[i][j][0]) * u0.x * w0);
                    z.y = rndf(silu_f(acc[i][j][1]) * u0.y * w0);
                    *(float2*)(C + (size_t)r0 * N + c0) = z;
                }
                if (r0 + 8 < M) {
                    float2 z;
                    z.x = rndf(silu_f(acc[i][j][2]) * u1.x * w1);
                    z.y = rndf(silu_f(acc[i][j][3]) * u1.y * w1);
                    *(float2*)(C + (size_t)(r0 + 8) * N + c0) = z;
                }
            }
        }
    }
}

// ---------------- fused gate+up+act launch ----------------
// grid (32, 32, NE+1): z<NE routed, z==NE shared expert.
__global__ __launch_bounds__(256, 2)
void gemm_guz(const float* __restrict__ Wg, const float* __restrict__ Wu,
              const float* __restrict__ Sg, const float* __restrict__ Su,
              int Tn) {
    int e  = blockIdx.z;
    int bx = blockIdx.x;
    int by = blockIdx.y;

    if (e < NE) {
        int M = d_cnt[e];
        if (by * BM >= M) return;
        guz_core<1>(d_xr, Wg + (size_t)e * IS * HD, Wu + (size_t)e * IS * HD,
                    d_bufZ + (size_t)e * TMAX * IS,
                    d_tok + e * TMAX, d_wgt + e * TMAX, M, HD, IS, by, bx);
    } else {
        if (by * BM >= Tn) return;
        guz_core<0>(d_xr, Sg, Su, d_sZ, nullptr, nullptr, Tn, HD, SIW, by, bx);
    }
}

// ============ down GEMM core (R12 mainloop) ============
template<int ATOMIC, int SCAT>
__device__ __forceinline__ void gemm_core(
    const float* __restrict__ A, const float* __restrict__ B,
    float* __restrict__ C, const int* __restrict__ tok,
    int M, int K, int N, int by, int bx)
{
    extern __shared__ float smem[];
    uint32_t sbase = smem_u32(smem);

    int tid  = threadIdx.x;
    int lane = tid & 31;
    int warp = tid >> 5;
    int wm   = warp & 1;
    int wn   = warp >> 1;

    int lq = (tid & 7) * 4;
    int lr = tid >> 3;
    const float* aP[4];
    const float* bP[4];
    #pragma unroll
    for (int i = 0; i < 4; i++) {
        int r = by * BM + i * 32 + lr;
        int src = (r < M) ? r : (M - 1);
        aP[i] = A + (size_t)src * K + lq;
        bP[i] = B + (size_t)(bx * BN + i * 32 + lr) * K + lq;
    }
    uint32_t dOffA = (uint32_t)((lr * LSTR + lq) * 4);
    int      sOffB = SM_A_FLOATS + lr * LSTR + lq;

    uint32_t aAddr[4];
    #pragma unroll
    for (int i = 0; i < 4; i++) {
        int row = wm * 64 + i * 16 + (lane & 15);
        int col = (lane >> 4) << 2;
        aAddr[i] = sbase + (uint32_t)((row * LSTR + col) << 2);
    }
    uint32_t bAddr[2];
    #pragma unroll
    for (int p = 0; p < 2; p++) {
        int nrow = wn * 32 + p * 16 + ((lane >> 4) << 3) + (lane & 7);
        int col  = ((lane >> 3) & 1) << 2;
        bAddr[p] = sbase + (uint32_t)(SM_A_FLOATS * 4) +
                   (uint32_t)((nrow * LSTR + col) << 2);
    }

    float acc[4][4][4];
    #pragma unroll
    for (int i = 0; i < 4; i++)
        #pragma unroll
        for (int j = 0; j < 4; j++)
            #pragma unroll
            for (int q = 0; q < 4; q++) acc[i][j][q] = 0.f;

    int NT = K / BKT;
    float4 bReg[4];

    auto load_chunkA = [&](int c) {
        uint32_t sb = sbase + (uint32_t)(c & 1) * STAGE_BYTES;
        int k0 = c * BKT;
        #pragma unroll
        for (int i = 0; i < 4; i++)
            CPA16(sb + dOffA + (uint32_t)(i * 32 * LSTR * 4), aP[i] + k0);
        CPA_COMMIT();
    };
    auto ldg_B = [&](int c) {
        int k0 = c * BKT;
        #pragma unroll
        for (int i = 0; i < 4; i++)
            bReg[i] = *(const float4*)(bP[i] + k0);
    };
    auto sts_B = [&](int c) {
        float* st = smem + (c & 1) * SM_STAGE + sOffB;
        #pragma unroll
        for (int i = 0; i < 4; i++) {
            float4 v = bReg[i];
            float4 o;
            o.x = rndf(v.x); o.y = rndf(v.y); o.z = rndf(v.z); o.w = rndf(v.w);
            *(float4*)(st + i * 32 * LSTR) = o;
        }
    };

    load_chunkA(0);
    ldg_B(0);
    sts_B(0);

    for (int s = 0; s < NT; s++) {
        CPA_WAIT(0);
        __syncthreads();

        if (s + 1 < NT) {
            ldg_B(s + 1);
            load_chunkA(s + 1);
        }

        uint32_t stOff = (uint32_t)(s & 1) * STAGE_BYTES;

        #pragma unroll
        for (int ks = 0; ks < BKT; ks += 8) {
            uint32_t kOff = stOff + (uint32_t)(ks << 2);
            unsigned a[4][4];
            #pragma unroll
            for (int i = 0; i < 4; i++)
                LDSM4(a[i][0], a[i][1], a[i][2], a[i][3], aAddr[i] + kOff);
            unsigned b[2][4];
            #pragma unroll
            for (int p = 0; p < 2; p++)
                LDSM4(b[p][0], b[p][1], b[p][2], b[p][3], bAddr[p] + kOff);
            #pragma unroll
            for (int j = 0; j < 4; j++) {
                unsigned b0 = b[j >> 1][(j & 1) * 2];
                unsigned b1 = b[j >> 1][(j & 1) * 2 + 1];
                #pragma unroll
                for (int i = 0; i < 4; i++)
                    mma_tf32(acc[i][j], a[i], b0, b1);
            }
        }

        if (s + 1 < NT) sts_B(s + 1);
    }

    #pragma unroll
    for (int i = 0; i < 4; i++) {
        int r0 = by * BM + wm * 64 + i * 16 + (lane >> 2);
        #pragma unroll
        for (int j = 0; j < 4; j++) {
            int c0 = bx * BN + wn * 32 + j * 8 + 2 * (lane & 3);
            if (ATOMIC) {
                if (r0 < M) {
                    int tr = SCAT ? tok[r0] : r0;
                    atomicAdd(C + (size_t)tr * N + c0,     acc[i][j][0]);
                    atomicAdd(C + (size_t)tr * N + c0 + 1, acc[i][j][1]);
                }
                if (r0 + 8 < M) {
                    int tr = SCAT ? tok[r0 + 8] : (r0 + 8);
                    atomicAdd(C + (size_t)tr * N + c0,     acc[i][j][2]);
                    atomicAdd(C + (size_t)tr * N + c0 + 1, acc[i][j][3]);
                }
            } else {
                if (r0 < M) {
                    *(float2*)(C + (size_t)r0 * N + c0) =
                        make_float2(acc[i][j][0], acc[i][j][1]);
                }
                if (r0 + 8 < M) {
                    *(float2*)(C + (size_t)(r0 + 8) * N + c0) =
                        make_float2(acc[i][j][2], acc[i][j][3]);
                }
            }
        }
    }
}

// shared-expert down: direct stores to out
__global__ __launch_bounds__(256, 2)
void gemm_sd(const float* __restrict__ Sd, float* __restrict__ out, int Tn) {
    if ((int)blockIdx.y * BM >= Tn) return;
    gemm_core<0, 0>(d_sZ, Sd, out, nullptr, Tn, SIW, HD, blockIdx.y, blockIdx.x);
}

// routed down: scatter-atomicAdd into out
__global__ __launch_bounds__(256, 2)
void gemm_rd(const float* __restrict__ Wd, float* __restrict__ out) {
    int e = blockIdx.z;
    int M = d_cnt[e];
    if ((int)blockIdx.y * BM >= M) return;
    gemm_core<1, 1>(d_bufZ + (size_t)e * TMAX * IS,
                    Wd + (size_t)e * HD * IS,
                    out, d_tok + e * TMAX, M, IS, HD, blockIdx.y, blockIdx.x);
}

// ---------------- launch ----------------
extern "C" void kernel_launch(void* const* d_in, const int* in_sizes, int n_in,
                              void* d_out, int out_size) {
    const float* x    = (const float*)d_in[0];
    const float* gw   = (const float*)d_in[1];
    const float* bias = (const float*)d_in[2];
    const float* Wg   = (const float*)d_in[3];
    const float* Wu   = (const float*)d_in[4];
    const float* Wd   = (const float*)d_in[5];
    const float* Sg   = (const float*)d_in[6];
    const float* Su   = (const float*)d_in[7];
    const float* Sd   = (const float*)d_in[8];
    float* out = (float*)d_out;

    int Tn = in_sizes[0] / HD;            // 4096 tokens
    int mt = (Tn + BM - 1) / BM;          // 32

    static int smem_set = 0;
    if (!smem_set) {
        cudaFuncSetAttribute(gemm_guz, cudaFuncAttributeMaxDynamicSharedMemorySize, DSMEM_BYTES);
        cudaFuncSetAttribute(gemm_sd,  cudaFuncAttributeMaxDynamicSharedMemorySize, DSMEM_BYTES);
        cudaFuncSetAttribute(gemm_rd,  cudaFuncAttributeMaxDynamicSharedMemorySize, DSMEM_BYTES);
        smem_set = 1;
    }

    zero_cnt_kernel<<<1, 32>>>();
    router_kernel<<<Tn, 128>>>(x, gw, bias);
    round_kernel<<<2048, 256>>>((const float4*)x, (int)((size_t)Tn * HD / 4));

    // fused gate+up+activation: 16 routed experts + shared, one launch
    gemm_guz<<<dim3(IS / 64, 32, NE + 1), 256, DSMEM_BYTES>>>(Wg, Wu, Sg, Su, Tn);

    // shared down (direct store) then routed down (atomicAdd) — stream-ordered
    gemm_sd<<<dim3(HD / BN, mt, 1), 256, DSMEM_BYTES>>>(Sd, out, Tn);
    gemm_rd<<<dim3(HD / BN, 32, NE), 256, DSMEM_BYTES>>>(Wd, out);

    (void)n_in; (void)out_size;
}

// round 16
// speedup vs baseline: 1.1167x; 1.0117x over previous
#include <cuda_runtime.h>
#include <math.h>
#include <stdint.h>

// Problem constants
#define HD   4096
#define IS   2048
#define NE   16
#define NK   4
#define SIW  2048
#define TMAX 4096

// GEMM tile: CTA 128x128, 8 warps, K-chunk 32
#define BM   128
#define BN   128
#define BKT  32
#define LSTR 36                              // padded row stride (floats)
#define SM_A_FLOATS (BM * LSTR)              // 4608
#define SM_STAGE    (2 * SM_A_FLOATS)        // A + B per stage = 9216 floats
#define STAGE_BYTES (SM_STAGE * 4)           // 36864
#define DSMEM_BYTES (2 * STAGE_BYTES)        // 73728

// ---------------- static device scratch ----------------
__device__ int   d_cnt[NE];
__device__ int   d_tok[NE * TMAX];
__device__ float d_wgt[NE * TMAX];
__device__ float d_bufZ[(size_t)NE * TMAX * IS];   // routed z (tf32-rounded)
__device__ float d_sZ[(size_t)TMAX * SIW];         // shared z (tf32-rounded)
__device__ float d_xr[(size_t)TMAX * HD];          // tf32-rounded x

// ---------------- helpers ----------------
__device__ __forceinline__ uint32_t smem_u32(const void* p) {
    uint32_t a;
    asm("{ .reg .u64 t; cvta.to.shared.u64 t, %1; cvt.u32.u64 %0, t; }" : "=r"(a) : "l"(p));
    return a;
}
__device__ __forceinline__ unsigned f2tf32(float f) {
    unsigned r;
    asm("cvt.rna.tf32.f32 %0, %1;" : "=r"(r) : "f"(f));
    return r;
}
__device__ __forceinline__ float rndf(float v) {
    return __uint_as_float(f2tf32(v));
}
__device__ __forceinline__ float silu_f(float v) {
    return v / (1.f + expf(-v));
}
#define CPA16(dst, src) \
    asm volatile("cp.async.cg.shared.global [%0], [%1], 16;" :: "r"(dst), "l"(src))
#define CPA_COMMIT() asm volatile("cp.async.commit_group;")
#define CPA_WAIT(n)  asm volatile("cp.async.wait_group %0;" :: "n"(n))

#define LDSM4(r0, r1, r2, r3, addr) \
    asm volatile("ldmatrix.sync.aligned.m8n8.x4.shared.b16 {%0,%1,%2,%3}, [%4];" \
                 : "=r"(r0), "=r"(r1), "=r"(r2), "=r"(r3) : "r"(addr))

__device__ __forceinline__ void mma_tf32(float* d, const unsigned* a, unsigned b0, unsigned b1) {
    asm volatile(
        "mma.sync.aligned.m16n8k8.row.col.f32.tf32.tf32.f32 "
        "{%0,%1,%2,%3}, {%4,%5,%6,%7}, {%8,%9}, {%0,%1,%2,%3};"
        : "+f"(d[0]), "+f"(d[1]), "+f"(d[2]), "+f"(d[3])
        : "r"(a[0]), "r"(a[1]), "r"(a[2]), "r"(a[3]), "r"(b0), "r"(b1));
}

// ---------------- small kernels ----------------
__global__ void zero_cnt_kernel() {
    if (threadIdx.x < NE) d_cnt[threadIdx.x] = 0;
}

// router + fused tf32 pre-rounding of x (row already staged in smem)
__global__ void router_kernel(const float* __restrict__ x,
                              const float* __restrict__ gw,
                              const float* __restrict__ bias) {
    __shared__ float sx[HD];
    __shared__ float sc[NE];
    int t = blockIdx.x;
    const float4* xr = (const float4*)(x + (size_t)t * HD);
    for (int i = threadIdx.x; i < HD / 4; i += blockDim.x)
        ((float4*)sx)[i] = xr[i];
    __syncthreads();

    // write tf32-rounded copy of this token row
    {
        float4* xo = (float4*)(d_xr + (size_t)t * HD);
        for (int i = threadIdx.x; i < HD / 4; i += blockDim.x) {
            float4 v = ((float4*)sx)[i];
            float4 o;
            o.x = rndf(v.x); o.y = rndf(v.y); o.z = rndf(v.z); o.w = rndf(v.w);
            xo[i] = o;
        }
    }

    int warp = threadIdx.x >> 5, lane = threadIdx.x & 31;
    int nwarp = blockDim.x >> 5;
    for (int e = warp; e < NE; e += nwarp) {
        const float* w = gw + (size_t)e * HD;
        float s = 0.f;
        for (int i = lane; i < HD; i += 32) s = fmaf(sx[i], w[i], s);
        #pragma unroll
        for (int o = 16; o > 0; o >>= 1) s += __shfl_xor_sync(0xffffffffu, s, o);
        if (lane == 0) sc[e] = 1.f / (1.f + expf(-s)) + bias[e];
    }
    __syncthreads();

    if (threadIdx.x == 0) {
        float v[NE];
        #pragma unroll
        for (int e = 0; e < NE; e++) v[e] = sc[e];
        int idx[NK]; float wv[NK]; float sum = 0.f;
        #pragma unroll
        for (int k = 0; k < NK; k++) {
            int bi = 0; float bv = -1e30f;
            #pragma unroll
            for (int e = 0; e < NE; e++) if (v[e] > bv) { bv = v[e]; bi = e; }
            idx[k] = bi; wv[k] = bv; v[bi] = -1e30f; sum += bv;
        }
        float inv = 1.f / (sum + 1e-20f);
        #pragma unroll
        for (int k = 0; k < NK; k++) {
            int e = idx[k];
            int pos = atomicAdd(&d_cnt[e], 1);
            d_tok[e * TMAX + pos] = t;
            d_wgt[e * TMAX + pos] = wv[k] * inv;
        }
    }
}

// ============ fused gate+up+act core (exchange-free) ============
// One CTA computes a 128x64 z-tile. B smem rows 0-63 = Wg rows,
// rows 64-127 = Wu rows (same 64 output cols). Each warp owns 16 z-cols and
// accumulates BOTH g (from lower B half) and u (upper half) with identical
// (row,col) lane mapping -> z = rndf(silu(g)*u*w) computed in-register.
template<int GATHER>
__device__ __forceinline__ void guz_core(
    const float* __restrict__ A,
    const float* __restrict__ Bg, const float* __restrict__ Bu,
    float* __restrict__ C, const int* __restrict__ tok,
    const float* __restrict__ wgt,
    int M, int K, int N, int by, int bx)
{
    extern __shared__ float smem[];
    uint32_t sbase = smem_u32(smem);

    int tid  = threadIdx.x;
    int lane = tid & 31;
    int warp = tid >> 5;
    int wm   = warp & 1;     // 2 warps along M (64 rows each)
    int wn   = warp >> 1;    // 4 warps along N (16 z-cols each)

    // ---- loader: thread owns (tid&7)*4 float offset, rows i*32 + (tid>>3) ----
    int lq = (tid & 7) * 4;
    int lr = tid >> 3;
    const float* aP[4];
    const float* bP[4];
    #pragma unroll
    for (int i = 0; i < 4; i++) {
        int r = by * BM + i * 32 + lr;
        int src;
        if (GATHER) src = (r < M) ? tok[r] : tok[0];
        else        src = (r < M) ? r : (M - 1);
        aP[i] = A + (size_t)src * K + lq;
    }
    bP[0] = Bg + (size_t)(bx * 64 + lr)      * K + lq;
    bP[1] = Bg + (size_t)(bx * 64 + 32 + lr) * K + lq;
    bP[2] = Bu + (size_t)(bx * 64 + lr)      * K + lq;
    bP[3] = Bu + (size_t)(bx * 64 + 32 + lr) * K + lq;

    uint32_t dOffA = (uint32_t)((lr * LSTR + lq) * 4);
    int      sOffB = SM_A_FLOATS + lr * LSTR + lq;

    uint32_t aAddr[4];
    #pragma unroll
    for (int i = 0; i < 4; i++) {
        int row = wm * 64 + i * 16 + (lane & 15);
        int col = (lane >> 4) << 2;
        aAddr[i] = sbase + (uint32_t)((row * LSTR + col) << 2);
    }
    uint32_t bAddrG, bAddrU;
    {
        int nrow = wn * 16 + ((lane >> 4) << 3) + (lane & 7);
        int col  = ((lane >> 3) & 1) << 2;
        bAddrG = sbase + (uint32_t)(SM_A_FLOATS * 4) +
                 (uint32_t)((nrow * LSTR + col) << 2);
        bAddrU = bAddrG + (uint32_t)((64 * LSTR) << 2);
    }

    float accG[4][2][4], accU[4][2][4];
    #pragma unroll
    for (int i = 0; i < 4; i++)
        #pragma unroll
        for (int j = 0; j < 2; j++)
            #pragma unroll
            for (int q = 0; q < 4; q++) { accG[i][j][q] = 0.f; accU[i][j][q] = 0.f; }

    int NT = K / BKT;
    float4 bReg[4];

    auto load_chunkA = [&](int c) {
        uint32_t sb = sbase + (uint32_t)(c & 1) * STAGE_BYTES;
        int k0 = c * BKT;
        #pragma unroll
        for (int i = 0; i < 4; i++)
            CPA16(sb + dOffA + (uint32_t)(i * 32 * LSTR * 4), aP[i] + k0);
        CPA_COMMIT();
    };
    auto ldg_B = [&](int c) {
        int k0 = c * BKT;
        #pragma unroll
        for (int i = 0; i < 4; i++)
            bReg[i] = *(const float4*)(bP[i] + k0);
    };
    auto sts_B = [&](int c) {
        float* st = smem + (c & 1) * SM_STAGE + sOffB;
        #pragma unroll
        for (int i = 0; i < 4; i++) {
            float4 v = bReg[i];
            float4 o;
            o.x = rndf(v.x); o.y = rndf(v.y); o.z = rndf(v.z); o.w = rndf(v.w);
            *(float4*)(st + i * 32 * LSTR) = o;
        }
    };

    load_chunkA(0);
    ldg_B(0);
    sts_B(0);

    for (int s = 0; s < NT; s++) {
        CPA_WAIT(0);
        __syncthreads();

        if (s + 1 < NT) {
            ldg_B(s + 1);
            load_chunkA(s + 1);
        }

        uint32_t stOff = (uint32_t)(s & 1) * STAGE_BYTES;

        #pragma unroll
        for (int ks = 0; ks < BKT; ks += 8) {
            uint32_t kOff = stOff + (uint32_t)(ks << 2);
            unsigned a[4][4];
            #pragma unroll
            for (int i = 0; i < 4; i++)
                LDSM4(a[i][0], a[i][1], a[i][2], a[i][3], aAddr[i] + kOff);
            unsigned bg[4], bu[4];
            LDSM4(bg[0], bg[1], bg[2], bg[3], bAddrG + kOff);
            LDSM4(bu[0], bu[1], bu[2], bu[3], bAddrU + kOff);
            #pragma unroll
            for (int j = 0; j < 2; j++) {
                #pragma unroll
                for (int i = 0; i < 4; i++)
                    mma_tf32(accG[i][j], a[i], bg[j * 2], bg[j * 2 + 1]);
                #pragma unroll
                for (int i = 0; i < 4; i++)
                    mma_tf32(accU[i][j], a[i], bu[j * 2], bu[j * 2 + 1]);
            }
        }

        if (s + 1 < NT) sts_B(s + 1);
    }

    // ---- in-register activation epilogue ----
    #pragma unroll
    for (int i = 0; i < 4; i++) {
        int rl = wm * 64 + i * 16 + (lane >> 2);
        int r0 = by * BM + rl;
        float w0 = 1.f, w1 = 1.f;
        if (GATHER) {
            if (r0 < M)     w0 = wgt[r0];
            if (r0 + 8 < M) w1 = wgt[r0 + 8];
        }
        #pragma unroll
        for (int j = 0; j < 2; j++) {
            int c0 = bx * 64 + wn * 16 + j * 8 + 2 * (lane & 3);
            if (r0 < M) {
                float2 z;
                z.x = rndf(silu_f(accG[i][j][0]) * accU[i][j][0] * w0);
                z.y = rndf(silu_f(accG[i][j][1]) * accU[i][j][1] * w0);
                *(float2*)(C + (size_t)r0 * N + c0) = z;
            }
            if (r0 + 8 < M) {
                float2 z;
                z.x = rndf(silu_f(accG[i][j][2]) * accU[i][j][2] * w1);
                z.y = rndf(silu_f(accG[i][j][3]) * accU[i][j][3] * w1);
                *(float2*)(C + (size_t)(r0 + 8) * N + c0) = z;
            }
        }
    }
}

// ---------------- fused gate+up+act launch ----------------
// grid (32, 32, NE+1): z<NE routed, z==NE shared expert.
__global__ __launch_bounds__(256, 2)
void gemm_guz(const float* __restrict__ Wg, const float* __restrict__ Wu,
              const float* __restrict__ Sg, const float* __restrict__ Su,
              int Tn) {
    int e  = blockIdx.z;
    int bx = blockIdx.x;
    int by = blockIdx.y;

    if (e < NE) {
        int M = d_cnt[e];
        if (by * BM >= M) return;
        guz_core<1>(d_xr, Wg + (size_t)e * IS * HD, Wu + (size_t)e * IS * HD,
                    d_bufZ + (size_t)e * TMAX * IS,
                    d_tok + e * TMAX, d_wgt + e * TMAX, M, HD, IS, by, bx);
    } else {
        if (by * BM >= Tn) return;
        guz_core<0>(d_xr, Sg, Su, d_sZ, nullptr, nullptr, Tn, HD, SIW, by, bx);
    }
}

// ============ down GEMM core (R12 mainloop) ============
template<int ATOMIC, int SCAT>
__device__ __forceinline__ void gemm_core(
    const float* __restrict__ A, const float* __restrict__ B,
    float* __restrict__ C, const int* __restrict__ tok,
    int M, int K, int N, int by, int bx)
{
    extern __shared__ float smem[];
    uint32_t sbase = smem_u32(smem);

    int tid  = threadIdx.x;
    int lane = tid & 31;
    int warp = tid >> 5;
    int wm   = warp & 1;
    int wn   = warp >> 1;

    int lq = (tid & 7) * 4;
    int lr = tid >> 3;
    const float* aP[4];
    const float* bP[4];
    #pragma unroll
    for (int i = 0; i < 4; i++) {
        int r = by * BM + i * 32 + lr;
        int src = (r < M) ? r : (M - 1);
        aP[i] = A + (size_t)src * K + lq;
        bP[i] = B + (size_t)(bx * BN + i * 32 + lr) * K + lq;
    }
    uint32_t dOffA = (uint32_t)((lr * LSTR + lq) * 4);
    int      sOffB = SM_A_FLOATS + lr * LSTR + lq;

    uint32_t aAddr[4];
    #pragma unroll
    for (int i = 0; i < 4; i++) {
        int row = wm * 64 + i * 16 + (lane & 15);
        int col = (lane >> 4) << 2;
        aAddr[i] = sbase + (uint32_t)((row * LSTR + col) << 2);
    }
    uint32_t bAddr[2];
    #pragma unroll
    for (int p = 0; p < 2; p++) {
        int nrow = wn * 32 + p * 16 + ((lane >> 4) << 3) + (lane & 7);
        int col  = ((lane >> 3) & 1) << 2;
        bAddr[p] = sbase + (uint32_t)(SM_A_FLOATS * 4) +
                   (uint32_t)((nrow * LSTR + col) << 2);
    }

    float acc[4][4][4];
    #pragma unroll
    for (int i = 0; i < 4; i++)
        #pragma unroll
        for (int j = 0; j < 4; j++)
            #pragma unroll
            for (int q = 0; q < 4; q++) acc[i][j][q] = 0.f;

    int NT = K / BKT;
    float4 bReg[4];

    auto load_chunkA = [&](int c) {
        uint32_t sb = sbase + (uint32_t)(c & 1) * STAGE_BYTES;
        int k0 = c * BKT;
        #pragma unroll
        for (int i = 0; i < 4; i++)
            CPA16(sb + dOffA + (uint32_t)(i * 32 * LSTR * 4), aP[i] + k0);
        CPA_COMMIT();
    };
    auto ldg_B = [&](int c) {
        int k0 = c * BKT;
        #pragma unroll
        for (int i = 0; i < 4; i++)
            bReg[i] = *(const float4*)(bP[i] + k0);
    };
    auto sts_B = [&](int c) {
        float* st = smem + (c & 1) * SM_STAGE + sOffB;
        #pragma unroll
        for (int i = 0; i < 4; i++) {
            float4 v = bReg[i];
            float4 o;
            o.x = rndf(v.x); o.y = rndf(v.y); o.z = rndf(v.z); o.w = rndf(v.w);
            *(float4*)(st + i * 32 * LSTR) = o;
        }
    };

    load_chunkA(0);
    ldg_B(0);
    sts_B(0);

    for (int s = 0; s < NT; s++) {
        CPA_WAIT(0);
        __syncthreads();

        if (s + 1 < NT) {
            ldg_B(s + 1);
            load_chunkA(s + 1);
        }

        uint32_t stOff = (uint32_t)(s & 1) * STAGE_BYTES;

        #pragma unroll
        for (int ks = 0; ks < BKT; ks += 8) {
            uint32_t kOff = stOff + (uint32_t)(ks << 2);
            unsigned a[4][4];
            #pragma unroll
            for (int i = 0; i < 4; i++)
                LDSM4(a[i][0], a[i][1], a[i][2], a[i][3], aAddr[i] + kOff);
            unsigned b[2][4];
            #pragma unroll
            for (int p = 0; p < 2; p++)
                LDSM4(b[p][0], b[p][1], b[p][2], b[p][3], bAddr[p] + kOff);
            #pragma unroll
            for (int j = 0; j < 4; j++) {
                unsigned b0 = b[j >> 1][(j & 1) * 2];
                unsigned b1 = b[j >> 1][(j & 1) * 2 + 1];
                #pragma unroll
                for (int i = 0; i < 4; i++)
                    mma_tf32(acc[i][j], a[i], b0, b1);
            }
        }

        if (s + 1 < NT) sts_B(s + 1);
    }

    #pragma unroll
    for (int i = 0; i < 4; i++) {
        int r0 = by * BM + wm * 64 + i * 16 + (lane >> 2);
        #pragma unroll
        for (int j = 0; j < 4; j++) {
            int c0 = bx * BN + wn * 32 + j * 8 + 2 * (lane & 3);
            if (ATOMIC) {
                if (r0 < M) {
                    int tr = SCAT ? tok[r0] : r0;
                    atomicAdd(C + (size_t)tr * N + c0,     acc[i][j][0]);
                    atomicAdd(C + (size_t)tr * N + c0 + 1, acc[i][j][1]);
                }
                if (r0 + 8 < M) {
                    int tr = SCAT ? tok[r0 + 8] : (r0 + 8);
                    atomicAdd(C + (size_t)tr * N + c0,     acc[i][j][2]);
                    atomicAdd(C + (size_t)tr * N + c0 + 1, acc[i][j][3]);
                }
            } else {
                if (r0 < M) {
                    *(float2*)(C + (size_t)r0 * N + c0) =
                        make_float2(acc[i][j][0], acc[i][j][1]);
                }
                if (r0 + 8 < M) {
                    *(float2*)(C + (size_t)(r0 + 8) * N + c0) =
                        make_float2(acc[i][j][2], acc[i][j][3]);
                }
            }
        }
    }
}

// shared-expert down: direct stores to out
__global__ __launch_bounds__(256, 2)
void gemm_sd(const float* __restrict__ Sd, float* __restrict__ out, int Tn) {
    if ((int)blockIdx.y * BM >= Tn) return;
    gemm_core<0, 0>(d_sZ, Sd, out, nullptr, Tn, SIW, HD, blockIdx.y, blockIdx.x);
}

// routed down: scatter-atomicAdd into out
__global__ __launch_bounds__(256, 2)
void gemm_rd(const float* __restrict__ Wd, float* __restrict__ out) {
    int e = blockIdx.z;
    int M = d_cnt[e];
    if ((int)blockIdx.y * BM >= M) return;
    gemm_core<1, 1>(d_bufZ + (size_t)e * TMAX * IS,
                    Wd + (size_t)e * HD * IS,
                    out, d_tok + e * TMAX, M, IS, HD, blockIdx.y, blockIdx.x);
}

// ---------------- launch ----------------
extern "C" void kernel_launch(void* const* d_in, const int* in_sizes, int n_in,
                              void* d_out, int out_size) {
    const float* x    = (const float*)d_in[0];
    const float* gw   = (const float*)d_in[1];
    const float* bias = (const float*)d_in[2];
    const float* Wg   = (const float*)d_in[3];
    const float* Wu   = (const float*)d_in[4];
    const float* Wd   = (const float*)d_in[5];
    const float* Sg   = (const float*)d_in[6];
    const float* Su   = (const float*)d_in[7];
    const float* Sd   = (const float*)d_in[8];
    float* out = (float*)d_out;

    int Tn = in_sizes[0] / HD;            // 4096 tokens
    int mt = (Tn + BM - 1) / BM;          // 32

    static int smem_set = 0;
    if (!smem_set) {
        cudaFuncSetAttribute(gemm_guz, cudaFuncAttributeMaxDynamicSharedMemorySize, DSMEM_BYTES);
        cudaFuncSetAttribute(gemm_sd,  cudaFuncAttributeMaxDynamicSharedMemorySize, DSMEM_BYTES);
        cudaFuncSetAttribute(gemm_rd,  cudaFuncAttributeMaxDynamicSharedMemorySize, DSMEM_BYTES);
        smem_set = 1;
    }

    zero_cnt_kernel<<<1, 32>>>();
    router_kernel<<<Tn, 128>>>(x, gw, bias);   // also writes tf32-rounded d_xr

    // fused gate+up+activation: 16 routed experts + shared, one launch
    gemm_guz<<<dim3(IS / 64, 32, NE + 1), 256, DSMEM_BYTES>>>(Wg, Wu, Sg, Su, Tn);

    // shared down (direct store) then routed down (atomicAdd) — stream-ordered
    gemm_sd<<<dim3(HD / BN, mt, 1), 256, DSMEM_BYTES>>>(Sd, out, Tn);
    gemm_rd<<<dim3(HD / BN, 32, NE), 256, DSMEM_BYTES>>>(Wd, out);

    (void)n_in; (void)out_size;
}